// round 2
// baseline (speedup 1.0000x reference)
#include <cuda_runtime.h>
#include <math.h>

#define BB   4096
#define LAT  128
#define HH   256
#define H4   1024
#define NOUT 88
#define TT   64
#define NL   5

// ---------------- device scratch (no cudaMalloc allowed) ----------------
__device__ float g_h[2][NL][BB * HH];      // ping-pong hidden state per layer
__device__ float g_c[NL][BB * HH];         // cell state (in-place)
__device__ float g_xp[BB * HH];            // latent projection
__device__ float g_gx0[BB * H4];           // constant layer-0 input gates (permuted, biases folded)
__device__ float g_wih_p[NL][H4 * HH];     // gate-interleaved w_ih
__device__ float g_whh_p[NL][H4 * HH];     // gate-interleaved w_hh
__device__ float g_bsum[NL][H4];           // (b_ih + b_hh) gate-interleaved
__device__ float g_y[(size_t)BB * TT * HH];// top-layer h over time -> out GEMM input

__device__ __forceinline__ float sigmf(float x) { return 1.f / (1.f + expf(-x)); }

// ---------------- init ----------------
__global__ void zero_kernel() {
    const int n = NL * BB * HH;
    float* h0 = &g_h[0][0][0];
    float* c0 = &g_c[0][0];
    for (int i = blockIdx.x * blockDim.x + threadIdx.x; i < n; i += gridDim.x * blockDim.x) {
        h0[i] = 0.f;
        c0[i] = 0.f;
    }
}

// permute gate dim: original n = g*256 + j  ->  np = j*4 + g  (g in {i,f,g,o})
__global__ void permute_kernel(const float* __restrict__ w_ih, const float* __restrict__ w_hh,
                               const float* __restrict__ b_ih, const float* __restrict__ b_hh) {
    const int total = NL * H4 * HH;
    for (int i = blockIdx.x * blockDim.x + threadIdx.x; i < total; i += gridDim.x * blockDim.x) {
        int l   = i / (H4 * HH);
        int rem = i - l * (H4 * HH);
        int n   = rem / HH;
        int k   = rem - n * HH;
        int gg  = n >> 8;
        int j   = n & (HH - 1);
        int np  = (j << 2) | gg;
        g_wih_p[l][np * HH + k] = w_ih[i];
        g_whh_p[l][np * HH + k] = w_hh[i];
        if (k == 0)
            g_bsum[l][np] = b_ih[l * H4 + n] + b_hh[l * H4 + n];
    }
}

// ---------------- shared GEMM tile core: BM=128, BN=64, BK=16, 256 thr, TM=8, TN=4 ----
__device__ __forceinline__ void gemm_accum(
    const float* __restrict__ A,   // [M, K] row-major
    const float* __restrict__ W,   // [N, K] row-major (C = A @ W^T)
    int m0, int n0, int K, float acc[8][4],
    float As[16][128], float Bs[16][64])
{
    const int tid = threadIdx.x;
    const int ty  = tid >> 4, tx = tid & 15;
    const int r   = tid >> 2, c4 = (tid & 3) << 2;
    for (int k0 = 0; k0 < K; k0 += 16) {
        float4 va0 = *(const float4*)(A + (size_t)(m0 + r)      * K + k0 + c4);
        float4 va1 = *(const float4*)(A + (size_t)(m0 + r + 64) * K + k0 + c4);
        float4 vb  = *(const float4*)(W + (size_t)(n0 + r)      * K + k0 + c4);
        As[c4 + 0][r] = va0.x; As[c4 + 1][r] = va0.y; As[c4 + 2][r] = va0.z; As[c4 + 3][r] = va0.w;
        As[c4 + 0][r + 64] = va1.x; As[c4 + 1][r + 64] = va1.y;
        As[c4 + 2][r + 64] = va1.z; As[c4 + 3][r + 64] = va1.w;
        Bs[c4 + 0][r] = vb.x; Bs[c4 + 1][r] = vb.y; Bs[c4 + 2][r] = vb.z; Bs[c4 + 3][r] = vb.w;
        __syncthreads();
        #pragma unroll
        for (int k = 0; k < 16; k++) {
            float4 a0 = *(const float4*)&As[k][ty * 8];
            float4 a1 = *(const float4*)&As[k][ty * 8 + 4];
            float4 b  = *(const float4*)&Bs[k][tx * 4];
            float ar[8] = {a0.x, a0.y, a0.z, a0.w, a1.x, a1.y, a1.z, a1.w};
            float br[4] = {b.x, b.y, b.z, b.w};
            #pragma unroll
            for (int i = 0; i < 8; i++)
                #pragma unroll
                for (int u = 0; u < 4; u++)
                    acc[i][u] = fmaf(ar[i], br[u], acc[i][u]);
        }
        __syncthreads();
    }
}

// ---------------- fused LSTM step (one layer, one timestep) ----------------
// Gate-interleaved N layout means each thread's 4 accumulator columns are exactly
// (i,f,g,o) of one hidden unit j -> cell update is fully thread-local.
template <bool HAS_IH, bool WRITE_Y>
__global__ __launch_bounds__(256) void lstm_step(int t, int l) {
    __shared__ float As[16][128];
    __shared__ float Bs[16][64];
    float acc[8][4] = {};
    const int m0 = blockIdx.y * 128, n0 = blockIdx.x * 64;
    const int rd = t & 1, wr = (t + 1) & 1;

    gemm_accum(g_h[rd][l], g_whh_p[l], m0, n0, HH, acc, As, Bs);
    if (HAS_IH)
        gemm_accum(g_h[wr][l - 1], g_wih_p[l], m0, n0, HH, acc, As, Bs);

    const int tid = threadIdx.x, ty = tid >> 4, tx = tid & 15;
    const int j = (n0 >> 2) + tx;
    float* c  = g_c[l];
    float* ho = g_h[wr][l];

    float4 bstat = make_float4(0.f, 0.f, 0.f, 0.f);
    if (HAS_IH) bstat = *(const float4*)(g_bsum[l] + n0 + tx * 4);

    #pragma unroll
    for (int i = 0; i < 8; i++) {
        const int m = m0 + ty * 8 + i;
        float4 bv = HAS_IH ? bstat
                           : *(const float4*)(g_gx0 + (size_t)m * H4 + n0 + tx * 4);
        float si = sigmf(acc[i][0] + bv.x);
        float sf = sigmf(acc[i][1] + bv.y);
        float tg = tanhf(acc[i][2] + bv.z);
        float so = sigmf(acc[i][3] + bv.w);
        const int idx = m * HH + j;
        float cn = fmaf(sf, c[idx], si * tg);
        c[idx] = cn;
        float hn = so * tanhf(cn);
        ho[idx] = hn;
        if (WRITE_Y)
            g_y[(size_t)m * (TT * HH) + (size_t)t * HH + j] = hn;
    }
}

// ---------------- latent projection: g_xp = x @ linear_w^T + linear_b ----------------
__global__ __launch_bounds__(256) void proj_kernel(const float* __restrict__ x,
                                                   const float* __restrict__ lw,
                                                   const float* __restrict__ lb) {
    __shared__ float As[16][128];
    __shared__ float Bs[16][64];
    float acc[8][4] = {};
    const int m0 = blockIdx.y * 128, n0 = blockIdx.x * 64;
    gemm_accum(x, lw, m0, n0, LAT, acc, As, Bs);
    const int tid = threadIdx.x, ty = tid >> 4, tx = tid & 15;
    #pragma unroll
    for (int i = 0; i < 8; i++) {
        const int m = m0 + ty * 8 + i;
        const int n = n0 + tx * 4;
        float4 bv = *(const float4*)(lb + n);
        float4 o = make_float4(acc[i][0] + bv.x, acc[i][1] + bv.y,
                               acc[i][2] + bv.z, acc[i][3] + bv.w);
        *(float4*)(g_xp + (size_t)m * HH + n) = o;
    }
}

// ---------------- constant layer-0 gates: g_gx0 = g_xp @ w_ih0_p^T + (b_ih0+b_hh0)_p ----
__global__ __launch_bounds__(256) void gx0_kernel() {
    __shared__ float As[16][128];
    __shared__ float Bs[16][64];
    float acc[8][4] = {};
    const int m0 = blockIdx.y * 128, n0 = blockIdx.x * 64;
    gemm_accum(g_xp, g_wih_p[0], m0, n0, HH, acc, As, Bs);
    const int tid = threadIdx.x, ty = tid >> 4, tx = tid & 15;
    float4 bv = *(const float4*)(g_bsum[0] + n0 + tx * 4);
    #pragma unroll
    for (int i = 0; i < 8; i++) {
        const int m = m0 + ty * 8 + i;
        const int n = n0 + tx * 4;
        float4 o = make_float4(acc[i][0] + bv.x, acc[i][1] + bv.y,
                               acc[i][2] + bv.z, acc[i][3] + bv.w);
        *(float4*)(g_gx0 + (size_t)m * H4 + n) = o;
    }
}

// ---------------- output: sigmoid(g_y[B*T,256] @ out_w^T + out_b), N=88 padded to 96 ----
__global__ __launch_bounds__(256) void out_kernel(const float* __restrict__ Wo,
                                                  const float* __restrict__ bo,
                                                  float* __restrict__ out) {
    __shared__ float As[16][128];
    __shared__ float Bs[16][96];
    float acc[8][6] = {};
    const int m0 = blockIdx.x * 128;
    const int tid = threadIdx.x, ty = tid >> 4, tx = tid & 15;
    const int r = tid >> 2, c4 = (tid & 3) << 2;
    for (int k0 = 0; k0 < HH; k0 += 16) {
        float4 va0 = *(const float4*)(g_y + (size_t)(m0 + r)      * HH + k0 + c4);
        float4 va1 = *(const float4*)(g_y + (size_t)(m0 + r + 64) * HH + k0 + c4);
        As[c4 + 0][r] = va0.x; As[c4 + 1][r] = va0.y; As[c4 + 2][r] = va0.z; As[c4 + 3][r] = va0.w;
        As[c4 + 0][r + 64] = va1.x; As[c4 + 1][r + 64] = va1.y;
        As[c4 + 2][r + 64] = va1.z; As[c4 + 3][r + 64] = va1.w;
        #pragma unroll
        for (int i2 = 0; i2 < 6; i2++) {
            int flat = tid + 256 * i2;      // 0..1535
            int row = flat >> 4, col = flat & 15;
            Bs[col][row] = (row < NOUT) ? Wo[row * HH + k0 + col] : 0.f;
        }
        __syncthreads();
        #pragma unroll
        for (int k = 0; k < 16; k++) {
            float4 a0 = *(const float4*)&As[k][ty * 8];
            float4 a1 = *(const float4*)&As[k][ty * 8 + 4];
            float ar[8] = {a0.x, a0.y, a0.z, a0.w, a1.x, a1.y, a1.z, a1.w};
            #pragma unroll
            for (int i = 0; i < 8; i++)
                #pragma unroll
                for (int u = 0; u < 6; u++)
                    acc[i][u] = fmaf(ar[i], Bs[k][tx * 6 + u], acc[i][u]);
        }
        __syncthreads();
    }
    #pragma unroll
    for (int i = 0; i < 8; i++) {
        const int m = m0 + ty * 8 + i;
        #pragma unroll
        for (int u = 0; u < 6; u++) {
            const int n = tx * 6 + u;
            if (n < NOUT)
                out[(size_t)m * NOUT + n] = sigmf(acc[i][u] + bo[n]);
        }
    }
}

// ---------------- host ----------------
extern "C" void kernel_launch(void* const* d_in, const int* in_sizes, int n_in,
                              void* d_out, int out_size) {
    const float* x   = (const float*)d_in[0];
    const float* lw  = (const float*)d_in[1];
    const float* lb  = (const float*)d_in[2];
    const float* wih = (const float*)d_in[3];
    const float* whh = (const float*)d_in[4];
    const float* bih = (const float*)d_in[5];
    const float* bhh = (const float*)d_in[6];
    const float* ow  = (const float*)d_in[7];
    const float* ob  = (const float*)d_in[8];
    float* out = (float*)d_out;

    zero_kernel<<<1024, 256>>>();
    permute_kernel<<<2048, 256>>>(wih, whh, bih, bhh);
    proj_kernel<<<dim3(HH / 64, BB / 128), 256>>>(x, lw, lb);
    gx0_kernel<<<dim3(H4 / 64, BB / 128), 256>>>();

    for (int t = 0; t < TT; t++) {
        lstm_step<false, false><<<dim3(H4 / 64, BB / 128), 256>>>(t, 0);
        lstm_step<true,  false><<<dim3(H4 / 64, BB / 128), 256>>>(t, 1);
        lstm_step<true,  false><<<dim3(H4 / 64, BB / 128), 256>>>(t, 2);
        lstm_step<true,  false><<<dim3(H4 / 64, BB / 128), 256>>>(t, 3);
        lstm_step<true,  true ><<<dim3(H4 / 64, BB / 128), 256>>>(t, 4);
    }

    out_kernel<<<(BB * TT) / 128, 256>>>(ow, ob, out);
}

// round 10
// speedup vs baseline: 2.2852x; 2.2852x over previous
#include <cuda_runtime.h>
#include <cuda_bf16.h>
#include <cstdint>
#include <math.h>

#define BB   4096
#define LAT  128
#define HH   256
#define H4   1024
#define NOUT 88
#define TT   64
#define NL   5

#define NTHREADS 256

// ---- smem staging: rows padded to 144B (72 bf16) -> conflict-free ldmatrix ----
#define ROWB   144
#define PLANE  18432          // 128 rows * 144B
#define AHI 0
#define ALO 18432
#define BHI 36864
#define BLO 55296
#define STAGE  73728
#define SMEMT  (2*STAGE)      // 147456 B

// ---------------- device scratch ----------------
__device__ __align__(256) __nv_bfloat16 g_hhi[(size_t)2 * NL * BB * HH];
__device__ __align__(256) __nv_bfloat16 g_hlo[(size_t)2 * NL * BB * HH];
__device__ __align__(256) float g_c[(size_t)NL * BB * HH];
__device__ __align__(256) float g_xp[BB * HH];
__device__ __align__(256) float g_gx0[(size_t)BB * H4];
__device__ __align__(256) __nv_bfloat16 g_wc_hi[(size_t)NL * H4 * 512]; // [wih|whh], np-permuted
__device__ __align__(256) __nv_bfloat16 g_wc_lo[(size_t)NL * H4 * 512];
__device__ __align__(256) float g_wih0_p[H4 * HH];
__device__ __align__(256) float g_bsum[NL * H4];
__device__ __align__(256) float g_y[(size_t)BB * TT * HH];

__device__ __forceinline__ float sigmf(float x) { return 1.f / (1.f + expf(-x)); }

__device__ __forceinline__ const __nv_bfloat16* HHI(int pp, int l) {
    return g_hhi + ((size_t)pp * NL + l) * (BB * HH);
}
__device__ __forceinline__ const __nv_bfloat16* HLO(int pp, int l) {
    return g_hlo + ((size_t)pp * NL + l) * (BB * HH);
}

// ---------------- PTX helpers (base ISA only) ----------------
__device__ __forceinline__ uint32_t smem_u32(const void* p) {
    uint32_t a;
    asm("{ .reg .u64 t; cvta.to.shared.u64 t, %1; cvt.u32.u64 %0, t; }" : "=r"(a) : "l"(p));
    return a;
}
__device__ __forceinline__ void cp16(uint32_t dst, const void* src) {
    asm volatile("cp.async.cg.shared.global [%0], [%1], 16;" :: "r"(dst), "l"(src));
}
__device__ __forceinline__ void cp_commit() {
    asm volatile("cp.async.commit_group;" ::: "memory");
}
__device__ __forceinline__ void cp_wait0() {
    asm volatile("cp.async.wait_group 0;" ::: "memory");
}
__device__ __forceinline__ void ldmat4(unsigned r[4], uint32_t a) {
    asm volatile("ldmatrix.sync.aligned.m8n8.x4.shared.b16 {%0,%1,%2,%3}, [%4];"
                 : "=r"(r[0]), "=r"(r[1]), "=r"(r[2]), "=r"(r[3]) : "r"(a));
}
__device__ __forceinline__ void ldmat2(unsigned r[2], uint32_t a) {
    asm volatile("ldmatrix.sync.aligned.m8n8.x2.shared.b16 {%0,%1}, [%2];"
                 : "=r"(r[0]), "=r"(r[1]) : "r"(a));
}
__device__ __forceinline__ void mma16816(float c[4], const unsigned a[4], const unsigned b[2]) {
    asm volatile("mma.sync.aligned.m16n8k16.row.col.f32.bf16.bf16.f32 "
                 "{%0,%1,%2,%3}, {%4,%5,%6,%7}, {%8,%9}, {%0,%1,%2,%3};"
                 : "+f"(c[0]), "+f"(c[1]), "+f"(c[2]), "+f"(c[3])
                 : "r"(a[0]), "r"(a[1]), "r"(a[2]), "r"(a[3]), "r"(b[0]), "r"(b[1]));
}

// ---------------- init / prep kernels ----------------
__global__ void zero_kernel() {
    uint32_t* p1 = (uint32_t*)g_hhi;
    uint32_t* p2 = (uint32_t*)g_hlo;
    uint32_t* p3 = (uint32_t*)g_c;
    const size_t nH = (size_t)2 * NL * BB * HH / 2;
    const size_t nC = (size_t)NL * BB * HH;
    for (size_t i = blockIdx.x * blockDim.x + threadIdx.x; i < nH; i += (size_t)gridDim.x * blockDim.x) {
        p1[i] = 0u; p2[i] = 0u;
    }
    for (size_t i = blockIdx.x * blockDim.x + threadIdx.x; i < nC; i += (size_t)gridDim.x * blockDim.x)
        p3[i] = 0u;
}

// permute gate dim for fragment-local epilogue:
// original n = g*256 + j  ->  np = (j>>3)*32 + g*8 + (j&7)
__global__ void permute_kernel(const float* __restrict__ w_ih, const float* __restrict__ w_hh,
                               const float* __restrict__ b_ih, const float* __restrict__ b_hh) {
    const int total = NL * H4 * HH;
    for (int i = blockIdx.x * blockDim.x + threadIdx.x; i < total; i += gridDim.x * blockDim.x) {
        int l   = i / (H4 * HH);
        int rem = i - l * (H4 * HH);
        int n   = rem / HH;
        int k   = rem - n * HH;
        int gg  = n >> 8;
        int j   = n & (HH - 1);
        int np  = ((j >> 3) << 5) | (gg << 3) | (j & 7);
        float vih = w_ih[i], vhh = w_hh[i];
        size_t wb = ((size_t)l * H4 + np) * 512;
        if (l == 0) {
            __nv_bfloat16 h1 = __float2bfloat16(vhh);
            g_wc_hi[wb + k] = h1;
            g_wc_lo[wb + k] = __float2bfloat16(vhh - __bfloat162float(h1));
            g_wih0_p[np * HH + k] = vih;
        } else {
            __nv_bfloat16 h1 = __float2bfloat16(vih);
            g_wc_hi[wb + k] = h1;
            g_wc_lo[wb + k] = __float2bfloat16(vih - __bfloat162float(h1));
            __nv_bfloat16 h2 = __float2bfloat16(vhh);
            g_wc_hi[wb + 256 + k] = h2;
            g_wc_lo[wb + 256 + k] = __float2bfloat16(vhh - __bfloat162float(h2));
        }
        if (k == 0)
            g_bsum[l * H4 + np] = b_ih[l * H4 + n] + b_hh[l * H4 + n];
    }
}

// ---------------- fp32 FFMA GEMM core (prep + output kernels) ----------------
__device__ __forceinline__ void gemm_accum(
    const float* __restrict__ A, const float* __restrict__ W,
    int m0, int n0, int K, float acc[8][4],
    float As[16][128], float Bs[16][64])
{
    const int tid = threadIdx.x;
    const int ty  = tid >> 4, tx = tid & 15;
    const int r   = tid >> 2, c4 = (tid & 3) << 2;
    for (int k0 = 0; k0 < K; k0 += 16) {
        float4 va0 = *(const float4*)(A + (size_t)(m0 + r)      * K + k0 + c4);
        float4 va1 = *(const float4*)(A + (size_t)(m0 + r + 64) * K + k0 + c4);
        float4 vb  = *(const float4*)(W + (size_t)(n0 + r)      * K + k0 + c4);
        As[c4 + 0][r] = va0.x; As[c4 + 1][r] = va0.y; As[c4 + 2][r] = va0.z; As[c4 + 3][r] = va0.w;
        As[c4 + 0][r + 64] = va1.x; As[c4 + 1][r + 64] = va1.y;
        As[c4 + 2][r + 64] = va1.z; As[c4 + 3][r + 64] = va1.w;
        Bs[c4 + 0][r] = vb.x; Bs[c4 + 1][r] = vb.y; Bs[c4 + 2][r] = vb.z; Bs[c4 + 3][r] = vb.w;
        __syncthreads();
        #pragma unroll
        for (int k = 0; k < 16; k++) {
            float4 a0 = *(const float4*)&As[k][ty * 8];
            float4 a1 = *(const float4*)&As[k][ty * 8 + 4];
            float4 b  = *(const float4*)&Bs[k][tx * 4];
            float ar[8] = {a0.x, a0.y, a0.z, a0.w, a1.x, a1.y, a1.z, a1.w};
            float br[4] = {b.x, b.y, b.z, b.w};
            #pragma unroll
            for (int i = 0; i < 8; i++)
                #pragma unroll
                for (int u = 0; u < 4; u++)
                    acc[i][u] = fmaf(ar[i], br[u], acc[i][u]);
        }
        __syncthreads();
    }
}

__global__ __launch_bounds__(256) void proj_kernel(const float* __restrict__ x,
                                                   const float* __restrict__ lw,
                                                   const float* __restrict__ lb) {
    __shared__ float As[16][128];
    __shared__ float Bs[16][64];
    float acc[8][4] = {};
    const int m0 = blockIdx.y * 128, n0 = blockIdx.x * 64;
    gemm_accum(x, lw, m0, n0, LAT, acc, As, Bs);
    const int tid = threadIdx.x, ty = tid >> 4, tx = tid & 15;
    #pragma unroll
    for (int i = 0; i < 8; i++) {
        const int m = m0 + ty * 8 + i;
        const int n = n0 + tx * 4;
        float4 bv = *(const float4*)(lb + n);
        float4 o = make_float4(acc[i][0] + bv.x, acc[i][1] + bv.y,
                               acc[i][2] + bv.z, acc[i][3] + bv.w);
        *(float4*)(g_xp + (size_t)m * HH + n) = o;
    }
}

__global__ __launch_bounds__(256) void gx0_kernel() {
    __shared__ float As[16][128];
    __shared__ float Bs[16][64];
    float acc[8][4] = {};
    const int m0 = blockIdx.y * 128, n0 = blockIdx.x * 64;
    gemm_accum(g_xp, g_wih0_p, m0, n0, HH, acc, As, Bs);
    const int tid = threadIdx.x, ty = tid >> 4, tx = tid & 15;
    float4 bv = *(const float4*)(g_bsum + n0 + tx * 4);
    #pragma unroll
    for (int i = 0; i < 8; i++) {
        const int m = m0 + ty * 8 + i;
        const int n = n0 + tx * 4;
        float4 o = make_float4(acc[i][0] + bv.x, acc[i][1] + bv.y,
                               acc[i][2] + bv.z, acc[i][3] + bv.w);
        *(float4*)(g_gx0 + (size_t)m * H4 + n) = o;
    }
}

__global__ __launch_bounds__(256) void out_kernel(const float* __restrict__ Wo,
                                                  const float* __restrict__ bo,
                                                  float* __restrict__ out) {
    __shared__ float As[16][128];
    __shared__ float Bs[16][96];
    float acc[8][6] = {};
    const int m0 = blockIdx.x * 128;
    const int tid = threadIdx.x, ty = tid >> 4, tx = tid & 15;
    const int r = tid >> 2, c4 = (tid & 3) << 2;
    for (int k0 = 0; k0 < HH; k0 += 16) {
        float4 va0 = *(const float4*)(g_y + (size_t)(m0 + r)      * HH + k0 + c4);
        float4 va1 = *(const float4*)(g_y + (size_t)(m0 + r + 64) * HH + k0 + c4);
        As[c4 + 0][r] = va0.x; As[c4 + 1][r] = va0.y; As[c4 + 2][r] = va0.z; As[c4 + 3][r] = va0.w;
        As[c4 + 0][r + 64] = va1.x; As[c4 + 1][r + 64] = va1.y;
        As[c4 + 2][r + 64] = va1.z; As[c4 + 3][r + 64] = va1.w;
        #pragma unroll
        for (int i2 = 0; i2 < 6; i2++) {
            int flat = tid + 256 * i2;
            int row = flat >> 4, col = flat & 15;
            Bs[col][row] = (row < NOUT) ? Wo[row * HH + k0 + col] : 0.f;
        }
        __syncthreads();
        #pragma unroll
        for (int k = 0; k < 16; k++) {
            float4 a0 = *(const float4*)&As[k][ty * 8];
            float4 a1 = *(const float4*)&As[k][ty * 8 + 4];
            float ar[8] = {a0.x, a0.y, a0.z, a0.w, a1.x, a1.y, a1.z, a1.w};
            #pragma unroll
            for (int i = 0; i < 8; i++)
                #pragma unroll
                for (int u = 0; u < 6; u++)
                    acc[i][u] = fmaf(ar[i], Bs[k][tx * 6 + u], acc[i][u]);
        }
        __syncthreads();
    }
    #pragma unroll
    for (int i = 0; i < 8; i++) {
        const int m = m0 + ty * 8 + i;
        #pragma unroll
        for (int u = 0; u < 6; u++) {
            const int n = tx * 6 + u;
            if (n < NOUT)
                out[(size_t)m * NOUT + n] = sigmf(acc[i][u] + bo[n]);
        }
    }
}

// ---------------- mma.sync LSTM step ----------------
__device__ __forceinline__ void load_stage(
    uint32_t sb, int s,
    const __nv_bfloat16* __restrict__ Ahi, const __nv_bfloat16* __restrict__ Alo,
    int aCol0, int m0,
    const __nv_bfloat16* __restrict__ Whi, const __nv_bfloat16* __restrict__ Wlo,
    int wCol0, int n0g, int tid)
{
    uint32_t base = sb + (uint32_t)s * STAGE;
    #pragma unroll
    for (int i = 0; i < 4; i++) {
        int c = tid + i * NTHREADS;          // 0..1023
        int row = c >> 3, c8 = c & 7;
        uint32_t d = base + (uint32_t)(row * ROWB + c8 * 16);
        size_t asrc = (size_t)(m0 + row) * HH + aCol0 + c8 * 8;
        cp16(d + AHI, Ahi + asrc);
        cp16(d + ALO, Alo + asrc);
        size_t bsrc = (size_t)(n0g + row) * 512 + wCol0 + c8 * 8;
        cp16(d + BHI, Whi + bsrc);
        cp16(d + BLO, Wlo + bsrc);
    }
    cp_commit();
}

template <bool L0, bool WRITE_Y>
__global__ __launch_bounds__(NTHREADS) void lstm_mma(int t, int l)
{
    extern __shared__ __align__(16) char smem[];
    const uint32_t sb = smem_u32(smem);
    const int tid = threadIdx.x, lane = tid & 31, wid = tid >> 5;
    const int wm = wid >> 2, wn = wid & 3;          // 2 x 4 warp grid
    const int m0 = blockIdx.y * 128;
    const int n0g = blockIdx.x * 128;
    const int rd = t & 1, wr = (t + 1) & 1;

    const __nv_bfloat16* Whi = g_wc_hi + (size_t)l * (H4 * 512);
    const __nv_bfloat16* Wlo = g_wc_lo + (size_t)l * (H4 * 512);

    const int NS = L0 ? 4 : 8;

    // ldmatrix per-thread address components
    const int arow = lane & 15;                      // rows 0-15 pattern
    const int akq  = (lane & 16) >> 1;               // +8 cols for quads 2,3
    const uint32_t aOff = (uint32_t)((wm * 64 + arow) * ROWB + akq * 2);
    const int brow = lane & 7;
    const int bkq  = (lane & 8);                     // +8 cols for threads 8-15
    const uint32_t bOff = (uint32_t)((wn * 32 + brow) * ROWB + bkq * 2);

    float acc[4][4][4] = {};                          // [mfrag][gate][c]

    // prologue: stage 0
    {
        const __nv_bfloat16 *Ah, *Al; int col;
        if (L0) { Ah = HHI(rd, l); Al = HLO(rd, l); col = 0; }
        else    { Ah = HHI(wr, l - 1); Al = HLO(wr, l - 1); col = 0; }
        load_stage(sb, 0, Ah, Al, col, m0, Whi, Wlo, 0, n0g, tid);
    }

    for (int kc = 0; kc < NS; kc++) {
        cp_wait0();
        __syncthreads();
        if (kc + 1 < NS) {
            const __nv_bfloat16 *Ah, *Al; int col;
            int kn = kc + 1;
            if (L0)          { Ah = HHI(rd, l);     Al = HLO(rd, l);     col = kn * 64; }
            else if (kn < 4) { Ah = HHI(wr, l - 1); Al = HLO(wr, l - 1); col = kn * 64; }
            else             { Ah = HHI(rd, l);     Al = HLO(rd, l);     col = (kn - 4) * 64; }
            load_stage(sb, kn & 1, Ah, Al, col, m0, Whi, Wlo, kn * 64, n0g, tid);
        }
        // compute stage kc
        const uint32_t stb = sb + (uint32_t)(kc & 1) * STAGE;
        #pragma unroll
        for (int ks = 0; ks < 4; ks++) {
            unsigned Ah[4][4], Al[4][4];
            #pragma unroll
            for (int mf = 0; mf < 4; mf++)
                ldmat4(Ah[mf], stb + AHI + aOff + mf * (16 * ROWB) + ks * 32);
            #pragma unroll
            for (int mf = 0; mf < 4; mf++)
                ldmat4(Al[mf], stb + ALO + aOff + mf * (16 * ROWB) + ks * 32);
            #pragma unroll
            for (int gate = 0; gate < 4; gate++) {
                unsigned Bh[2], Bl[2];
                ldmat2(Bh, stb + BHI + bOff + gate * (8 * ROWB) + ks * 32);
                ldmat2(Bl, stb + BLO + bOff + gate * (8 * ROWB) + ks * 32);
                #pragma unroll
                for (int mf = 0; mf < 4; mf++) {
                    mma16816(acc[mf][gate], Ah[mf], Bh);
                    mma16816(acc[mf][gate], Ah[mf], Bl);
                    mma16816(acc[mf][gate], Al[mf], Bh);
                }
            }
        }
    }

    // ---- epilogue: fragment-local cell update ----
    const int g8 = lane >> 2, tig = lane & 3;
    const int nwb = n0g + wn * 32;                       // np base of this warp
    const int j0 = (blockIdx.x * 4 + wn) * 8 + 2 * tig;  // hidden-unit pair base
    float* cbase = g_c + (size_t)l * (BB * HH);
    __nv_bfloat16* hHi = (__nv_bfloat16*)HHI(wr, l);
    __nv_bfloat16* hLo = (__nv_bfloat16*)HLO(wr, l);

    float2 bb[4];
    if (!L0) {
        #pragma unroll
        for (int g = 0; g < 4; g++)
            bb[g] = *(const float2*)(g_bsum + l * H4 + nwb + g * 8 + 2 * tig);
    }

    #pragma unroll
    for (int mf = 0; mf < 4; mf++) {
        #pragma unroll
        for (int rs = 0; rs < 2; rs++) {
            const int m = m0 + wm * 64 + mf * 16 + g8 + rs * 8;
            float2 bv[4];
            if (L0) {
                const float* grow = g_gx0 + (size_t)m * H4 + nwb;
                #pragma unroll
                for (int g = 0; g < 4; g++) bv[g] = *(const float2*)(grow + g * 8 + 2 * tig);
            } else {
                #pragma unroll
                for (int g = 0; g < 4; g++) bv[g] = bb[g];
            }
            const int c0 = rs * 2, c1 = rs * 2 + 1;
            float xi0 = acc[mf][0][c0] + bv[0].x, xi1 = acc[mf][0][c1] + bv[0].y;
            float xf0 = acc[mf][1][c0] + bv[1].x, xf1 = acc[mf][1][c1] + bv[1].y;
            float xg0 = acc[mf][2][c0] + bv[2].x, xg1 = acc[mf][2][c1] + bv[2].y;
            float xo0 = acc[mf][3][c0] + bv[3].x, xo1 = acc[mf][3][c1] + bv[3].y;

            float2 cc = *(float2*)(cbase + (size_t)m * HH + j0);
            float cn0 = fmaf(sigmf(xf0), cc.x, sigmf(xi0) * tanhf(xg0));
            float cn1 = fmaf(sigmf(xf1), cc.y, sigmf(xi1) * tanhf(xg1));
            *(float2*)(cbase + (size_t)m * HH + j0) = make_float2(cn0, cn1);

            float h0 = sigmf(xo0) * tanhf(cn0);
            float h1 = sigmf(xo1) * tanhf(cn1);

            __nv_bfloat162 hh, hl;
            hh.x = __float2bfloat16(h0);
            hh.y = __float2bfloat16(h1);
            hl.x = __float2bfloat16(h0 - __bfloat162float(hh.x));
            hl.y = __float2bfloat16(h1 - __bfloat162float(hh.y));
            *(__nv_bfloat162*)(hHi + (size_t)m * HH + j0) = hh;
            *(__nv_bfloat162*)(hLo + (size_t)m * HH + j0) = hl;
            if (WRITE_Y)
                *(float2*)(g_y + (size_t)m * (TT * HH) + (size_t)t * HH + j0) = make_float2(h0, h1);
        }
    }
}

// ---------------- host ----------------
extern "C" void kernel_launch(void* const* d_in, const int* in_sizes, int n_in,
                              void* d_out, int out_size) {
    const float* x   = (const float*)d_in[0];
    const float* lw  = (const float*)d_in[1];
    const float* lb  = (const float*)d_in[2];
    const float* wih = (const float*)d_in[3];
    const float* whh = (const float*)d_in[4];
    const float* bih = (const float*)d_in[5];
    const float* bhh = (const float*)d_in[6];
    const float* ow  = (const float*)d_in[7];
    const float* ob  = (const float*)d_in[8];
    float* out = (float*)d_out;

    cudaFuncSetAttribute((const void*)lstm_mma<true,  false>, cudaFuncAttributeMaxDynamicSharedMemorySize, SMEMT);
    cudaFuncSetAttribute((const void*)lstm_mma<false, false>, cudaFuncAttributeMaxDynamicSharedMemorySize, SMEMT);
    cudaFuncSetAttribute((const void*)lstm_mma<false, true >, cudaFuncAttributeMaxDynamicSharedMemorySize, SMEMT);

    zero_kernel<<<1024, 256>>>();
    permute_kernel<<<2048, 256>>>(wih, whh, bih, bhh);
    proj_kernel<<<dim3(HH / 64, BB / 128), 256>>>(x, lw, lb);
    gx0_kernel<<<dim3(H4 / 64, BB / 128), 256>>>();

    dim3 g(H4 / 128, BB / 128);   // (8, 32) = 256 CTAs
    for (int t = 0; t < TT; t++) {
        lstm_mma<true,  false><<<g, NTHREADS, SMEMT>>>(t, 0);
        lstm_mma<false, false><<<g, NTHREADS, SMEMT>>>(t, 1);
        lstm_mma<false, false><<<g, NTHREADS, SMEMT>>>(t, 2);
        lstm_mma<false, false><<<g, NTHREADS, SMEMT>>>(t, 3);
        lstm_mma<false, true ><<<g, NTHREADS, SMEMT>>>(t, 4);
    }

    out_kernel<<<(BB * TT) / 128, 256>>>(ow, ob, out);
}